// round 1
// baseline (speedup 1.0000x reference)
#include <cuda_runtime.h>
#include <cuda_bf16.h>
#include <math.h>

#define BATCH 4
#define CDIM  256
#define CQK   32
#define NPIX  4096   // 64*64

// Scratch (static device globals: allowed; no allocations)
__device__ float g_Q[BATCH * NPIX * CQK];
__device__ float g_K[BATCH * NPIX * CQK];
__device__ float g_V[BATCH * NPIX * CDIM];

// ---------------------------------------------------------------------------
// Projection kernel: per pixel n, q = Wq@x + bq, k = Wk@x + bk, v = Wv@x + bv
// x layout: [B, C, N] (channel-major). 512 CTAs = B * N/32, 256 threads.
// Thread (n = tid%32, g = tid/32): 4 q rows, 4 k rows, 32 v rows.
// ---------------------------------------------------------------------------
__global__ __launch_bounds__(256) void proj_kernel(
    const float* __restrict__ x,
    const float* __restrict__ Wq, const float* __restrict__ bq,
    const float* __restrict__ Wk, const float* __restrict__ bk,
    const float* __restrict__ Wv, const float* __restrict__ bv)
{
    const int b  = blockIdx.y;
    const int n0 = blockIdx.x * 32;

    // x tile staged transposed: xs[n][c], row stride 260 (16B-aligned, 4-way conflict tolerable)
    __shared__ float xs[32 * 260];

    const int tid = threadIdx.x;
    for (int idx = tid; idx < 32 * 256; idx += 256) {
        int i = idx & 31;        // pixel within tile (coalesced global read over i)
        int c = idx >> 5;        // channel
        xs[i * 260 + c] = x[(b * CDIM + c) * NPIX + n0 + i];
    }
    __syncthreads();

    const int n = tid & 31;
    const int g = tid >> 5;          // 0..7

    float accq[4] = {0.f, 0.f, 0.f, 0.f};
    float acck[4] = {0.f, 0.f, 0.f, 0.f};
    float accv[32];
#pragma unroll
    for (int j = 0; j < 32; j++) accv[j] = 0.f;

    const float* xrow = &xs[n * 260];

#pragma unroll 2
    for (int c = 0; c < 256; c += 4) {
        const float4 xv = *(const float4*)&xrow[c];
#pragma unroll
        for (int j = 0; j < 4; j++) {
            const float4 w = *(const float4*)&Wq[(g * 4 + j) * CDIM + c];
            accq[j] += xv.x * w.x + xv.y * w.y + xv.z * w.z + xv.w * w.w;
        }
#pragma unroll
        for (int j = 0; j < 4; j++) {
            const float4 w = *(const float4*)&Wk[(g * 4 + j) * CDIM + c];
            acck[j] += xv.x * w.x + xv.y * w.y + xv.z * w.z + xv.w * w.w;
        }
#pragma unroll
        for (int j = 0; j < 32; j++) {
            const float4 w = *(const float4*)&Wv[(g * 32 + j) * CDIM + c];
            accv[j] += xv.x * w.x + xv.y * w.y + xv.z * w.z + xv.w * w.w;
        }
    }

    const int nglob = b * NPIX + n0 + n;
    float* qdst = &g_Q[nglob * CQK + g * 4];
    float* kdst = &g_K[nglob * CQK + g * 4];
#pragma unroll
    for (int j = 0; j < 4; j++) {
        qdst[j] = accq[j] + bq[g * 4 + j];
        kdst[j] = acck[j] + bk[g * 4 + j];
    }
    float* vdst = &g_V[nglob * CDIM + g * 32];
#pragma unroll
    for (int j = 0; j < 32; j++) {
        vdst[j] = accv[j] + bv[g * 32 + j];
    }
}

// ---------------------------------------------------------------------------
// Flash attention kernel. 512 CTAs = B * N/32 (32 queries each), 256 threads.
// Thread (q = tid%32, g = tid/32): owns V-channel slice [g*32, g*32+32).
// 128 key tiles of 32; online softmax handled by warp 0 (one thread per query).
// Epilogue writes out[b, c, n] = gamma * acc[c] / l  (transposed, coalesced over n).
// ---------------------------------------------------------------------------
__global__ __launch_bounds__(256) void attn_kernel(
    float* __restrict__ out, const float* __restrict__ gamma)
{
    const int b  = blockIdx.y;
    const int q0 = blockIdx.x * 32;

    __shared__ float Ks[32 * 32];            // K tile [m][d], warp-uniform reads
    __shared__ float Vs[32 * 256];           // V tile [m][c], warp-uniform float4 reads
    __shared__ float Ssm[32 * 33];           // scores / probs, pad 33 => conflict-free
    __shared__ float alpha_s[32];
    __shared__ float scale_s[32];

    const int tid = threadIdx.x;
    const int q = tid & 31;
    const int g = tid >> 5;

    // Q row for this query, kept in registers for all 128 tiles
    float qreg[CQK];
    {
        const float* Qp = &g_Q[(b * NPIX + q0 + q) * CQK];
#pragma unroll
        for (int d = 0; d < CQK; d += 4) {
            const float4 t = *(const float4*)&Qp[d];
            qreg[d] = t.x; qreg[d + 1] = t.y; qreg[d + 2] = t.z; qreg[d + 3] = t.w;
        }
    }

    float acc[32];
#pragma unroll
    for (int j = 0; j < 32; j++) acc[j] = 0.f;
    float m_run = -INFINITY;   // valid only in warp 0 (thread q)
    float l_run = 0.f;

    const int ldr = tid >> 3;            // 0..31: row for tile loads
    const int ldc = (tid & 7) * 4;       // 0,4,...,28: col base

    for (int t = 0; t < NPIX / 32; t++) {
        const int m0 = t * 32;

        // Load K tile (1024 floats) and V tile (8192 floats), coalesced float4
        *(float4*)&Ks[ldr * 32 + ldc] =
            *(const float4*)&g_K[(b * NPIX + m0 + ldr) * CQK + ldc];
        const float* vsrc = &g_V[(b * NPIX + m0 + ldr) * CDIM];
        float* vdst = &Vs[ldr * 256];
#pragma unroll
        for (int cc = 0; cc < 8; cc++) {
            const int c = ldc + cc * 32;
            *(float4*)&vdst[c] = *(const float4*)&vsrc[c];
        }
        __syncthreads();

        // Scores: thread computes S[q][g*4 + j], j = 0..3
#pragma unroll
        for (int j = 0; j < 4; j++) {
            const int kk = g * 4 + j;
            const float* krow = &Ks[kk * 32];
            float s = 0.f;
#pragma unroll
            for (int d = 0; d < CQK; d += 4) {
                const float4 k4 = *(const float4*)&krow[d];
                s += qreg[d] * k4.x + qreg[d + 1] * k4.y
                   + qreg[d + 2] * k4.z + qreg[d + 3] * k4.w;
            }
            Ssm[q * 33 + kk] = s;
        }
        __syncthreads();

        // Online softmax: warp 0, one thread per query row
        if (tid < 32) {
            float* row = &Ssm[tid * 33];
            float tm = row[0];
#pragma unroll
            for (int j = 1; j < 32; j++) tm = fmaxf(tm, row[j]);
            const float mnew = fmaxf(m_run, tm);
            const float al = __expf(m_run - mnew);   // exp(-inf)=0 on first tile
            float ls = 0.f;
#pragma unroll
            for (int j = 0; j < 32; j++) {
                const float p = __expf(row[j] - mnew);
                row[j] = p;
                ls += p;
            }
            l_run = l_run * al + ls;
            m_run = mnew;
            alpha_s[tid] = al;
        }
        __syncthreads();

        // Rescale accumulators, then accumulate P·V for this thread's channel slice
        const float al = alpha_s[q];
#pragma unroll
        for (int j = 0; j < 32; j++) acc[j] *= al;

        const float* srow = &Ssm[q * 33];
#pragma unroll 4
        for (int m = 0; m < 32; m++) {
            const float pm = srow[m];
            const float* vrow = &Vs[m * 256 + g * 32];
#pragma unroll
            for (int j = 0; j < 32; j += 4) {
                const float4 v4 = *(const float4*)&vrow[j];
                acc[j]     += pm * v4.x;
                acc[j + 1] += pm * v4.y;
                acc[j + 2] += pm * v4.z;
                acc[j + 3] += pm * v4.w;
            }
        }
        __syncthreads();   // protect Ks/Vs/Ssm before next tile's loads
    }

    // Epilogue
    if (tid < 32) scale_s[tid] = 1.f / l_run;
    __syncthreads();
    const float sc = scale_s[q] * gamma[0];
    const int nn = q0 + q;
    float* obase = &out[(size_t)b * CDIM * NPIX + nn];
#pragma unroll
    for (int j = 0; j < 32; j++) {
        obase[(size_t)(g * 32 + j) * NPIX] = acc[j] * sc;   // coalesced over q lanes
    }
}

// ---------------------------------------------------------------------------
// Inputs (metadata order): x, Wq, bq, Wk, bk, Wv, bv, gamma. Output: float32.
// ---------------------------------------------------------------------------
extern "C" void kernel_launch(void* const* d_in, const int* in_sizes, int n_in,
                              void* d_out, int out_size)
{
    const float* x     = (const float*)d_in[0];
    const float* Wq    = (const float*)d_in[1];
    const float* bq    = (const float*)d_in[2];
    const float* Wk    = (const float*)d_in[3];
    const float* bk    = (const float*)d_in[4];
    const float* Wv    = (const float*)d_in[5];
    const float* bv    = (const float*)d_in[6];
    const float* gamma = (const float*)d_in[7];
    float* out = (float*)d_out;

    dim3 grid(NPIX / 32, BATCH);
    proj_kernel<<<grid, 256>>>(x, Wq, bq, Wk, bk, Wv, bv);
    attn_kernel<<<grid, 256>>>(out, gamma);
}

// round 2
// speedup vs baseline: 4.2090x; 4.2090x over previous
#include <cuda_runtime.h>
#include <cuda_fp16.h>
#include <cuda_bf16.h>
#include <math.h>
#include <stdint.h>

#define BATCH 4
#define CDIM  256
#define CQK   32
#define NPIX  4096   // 64*64

// fp16 scratch (static device globals: allowed)
__device__ __half g_Qh[BATCH * NPIX * CQK];
__device__ __half g_Kh[BATCH * NPIX * CQK];
__device__ __half g_VhT[(size_t)BATCH * CDIM * NPIX];   // [B][C][N] transposed

// ---------------------------------------------------------------------------
// Projection kernel (fp32 compute, fp16 outputs).
// ---------------------------------------------------------------------------
__global__ __launch_bounds__(256) void proj_kernel(
    const float* __restrict__ x,
    const float* __restrict__ Wq, const float* __restrict__ bq,
    const float* __restrict__ Wk, const float* __restrict__ bk,
    const float* __restrict__ Wv, const float* __restrict__ bv)
{
    const int b  = blockIdx.y;
    const int n0 = blockIdx.x * 32;

    __shared__ float xs[32 * 260];

    const int tid = threadIdx.x;
    for (int idx = tid; idx < 32 * 256; idx += 256) {
        int i = idx & 31;
        int c = idx >> 5;
        xs[i * 260 + c] = x[(b * CDIM + c) * NPIX + n0 + i];
    }
    __syncthreads();

    const int n = tid & 31;
    const int g = tid >> 5;

    float accq[4] = {0.f, 0.f, 0.f, 0.f};
    float acck[4] = {0.f, 0.f, 0.f, 0.f};
    float accv[32];
#pragma unroll
    for (int j = 0; j < 32; j++) accv[j] = 0.f;

    const float* xrow = &xs[n * 260];

#pragma unroll 2
    for (int c = 0; c < 256; c += 4) {
        const float4 xv = *(const float4*)&xrow[c];
#pragma unroll
        for (int j = 0; j < 4; j++) {
            const float4 w = *(const float4*)&Wq[(g * 4 + j) * CDIM + c];
            accq[j] += xv.x * w.x + xv.y * w.y + xv.z * w.z + xv.w * w.w;
        }
#pragma unroll
        for (int j = 0; j < 4; j++) {
            const float4 w = *(const float4*)&Wk[(g * 4 + j) * CDIM + c];
            acck[j] += xv.x * w.x + xv.y * w.y + xv.z * w.z + xv.w * w.w;
        }
#pragma unroll
        for (int j = 0; j < 32; j++) {
            const float4 w = *(const float4*)&Wv[(g * 32 + j) * CDIM + c];
            accv[j] += xv.x * w.x + xv.y * w.y + xv.z * w.z + xv.w * w.w;
        }
    }

    const int nglob = b * NPIX + n0 + n;
#pragma unroll
    for (int j = 0; j < 4; j++) {
        g_Qh[nglob * CQK + g * 4 + j] = __float2half_rn(accq[j] + bq[g * 4 + j]);
        g_Kh[nglob * CQK + g * 4 + j] = __float2half_rn(acck[j] + bk[g * 4 + j]);
    }
#pragma unroll
    for (int j = 0; j < 32; j++) {
        g_VhT[((size_t)b * CDIM + g * 32 + j) * NPIX + n0 + n] =
            __float2half_rn(accv[j] + bv[g * 32 + j]);
    }
}

// ---------------------------------------------------------------------------
// Flash attention with mma.sync.m16n8k16 fp16 (fp32 accumulate).
// CTA: 64 queries, 256 threads (8 warps). Key tiles of 64.
// ---------------------------------------------------------------------------
#define QTILE  64
#define KTILE  64
#define QK_PAD 40   // halves per row, Qs/Ks (conflict-free fragment loads)
#define V_PAD  72   // halves per row, VsT
#define S_PAD  66   // floats per row, Ssm
#define P_PAD  70   // halves per row, Ps

// smem byte offsets
#define OFF_QS    0        // 64*40*2   = 5120
#define OFF_KS    5120     // 5120
#define OFF_VST   10240    // 256*72*2  = 36864 (also aliased as Obuf: 128*66*4)
#define OFF_SSM   47104    // 64*66*4   = 16896
#define OFF_PS    64000    // 64*70*2   = 8960
#define OFF_PMAX  72960    // 4*64*4
#define OFF_PSUM  73984    // 4*64*4
#define OFF_MS    75008    // 64*4
#define OFF_ALPHA 75264    // 64*4
#define OFF_LINV  75520    // 64*4
#define SMEM_TOTAL 75776
#define OB_PAD 66

__device__ __forceinline__ void mma16816(
    float& c0, float& c1, float& c2, float& c3,
    uint32_t a0, uint32_t a1, uint32_t a2, uint32_t a3,
    uint32_t b0, uint32_t b1)
{
    asm volatile(
        "mma.sync.aligned.m16n8k16.row.col.f32.f16.f16.f32 "
        "{%0,%1,%2,%3}, {%4,%5,%6,%7}, {%8,%9}, {%0,%1,%2,%3};\n"
        : "+f"(c0), "+f"(c1), "+f"(c2), "+f"(c3)
        : "r"(a0), "r"(a1), "r"(a2), "r"(a3), "r"(b0), "r"(b1));
}

__global__ __launch_bounds__(256, 2) void attn_kernel(
    float* __restrict__ out, const float* __restrict__ gamma)
{
    extern __shared__ char sm[];
    __half* Qs    = (__half*)(sm + OFF_QS);
    __half* Ks    = (__half*)(sm + OFF_KS);
    __half* VsT   = (__half*)(sm + OFF_VST);
    float*  Ssm   = (float*)(sm + OFF_SSM);
    __half* Ps    = (__half*)(sm + OFF_PS);
    float*  pmax  = (float*)(sm + OFF_PMAX);
    float*  psum  = (float*)(sm + OFF_PSUM);
    float*  m_s   = (float*)(sm + OFF_MS);
    float*  alp_s = (float*)(sm + OFF_ALPHA);
    float*  linv  = (float*)(sm + OFF_LINV);
    float*  Obuf  = (float*)(sm + OFF_VST);   // alias, used only in epilogue

    const int b   = blockIdx.y;
    const int q0  = blockIdx.x * QTILE;
    const int tid = threadIdx.x;
    const int w   = tid >> 5;
    const int lane = tid & 31;
    const int g = lane >> 2;   // mma groupID
    const int t = lane & 3;    // thread-in-group

    const size_t bN = (size_t)b * NPIX;

    // QK-phase warp mapping: S rows 16*(w&3), cols 32*(w>>2)
    const int qk_rb = 16 * (w & 3);
    const int qk_cb = 32 * (w >> 2);
    // PV-phase warp mapping: out rows 32*(w&1), cols 64*(w>>1)
    const int pv_qb = 32 * (w & 1);
    const int pv_cb = 64 * (w >> 1);

    // softmax mapping
    const int sq   = tid & 63;
    const int part = tid >> 6;

    // Load Q tile once: 64 rows x 32 halves
    {
        int row = tid >> 2, seg = tid & 3;
        *(uint4*)&Qs[row * QK_PAD + seg * 8] =
            *(const uint4*)&g_Qh[(bN + q0 + row) * CQK + seg * 8];
    }
    __syncthreads();

    // Preload Q fragments (persistent across all key tiles)
    uint32_t qa[2][4];
#pragma unroll
    for (int s = 0; s < 2; s++) {
        const __half* base = &Qs[(qk_rb + g) * QK_PAD + 2 * t + 16 * s];
        qa[s][0] = *(const uint32_t*)base;
        qa[s][2] = *(const uint32_t*)(base + 8);
        const __half* b8 = base + 8 * QK_PAD;
        qa[s][1] = *(const uint32_t*)b8;
        qa[s][3] = *(const uint32_t*)(b8 + 8);
    }

    float acc[2][8][4];
#pragma unroll
    for (int i = 0; i < 2; i++)
#pragma unroll
        for (int j = 0; j < 8; j++)
#pragma unroll
            for (int k = 0; k < 4; k++) acc[i][j][k] = 0.f;

    float m_run = -INFINITY, l_run = 0.f, alpha_reg = 0.f;

    for (int kt = 0; kt < NPIX / KTILE; kt++) {
        const int m0 = kt * KTILE;
        __syncthreads();   // previous iter's PV reads done before overwriting tiles

        // Load K tile: 64 x 32 halves
        {
            int row = tid >> 2, seg = tid & 3;
            *(uint4*)&Ks[row * QK_PAD + seg * 8] =
                *(const uint4*)&g_Kh[(bN + m0 + row) * CQK + seg * 8];
        }
        // Load V^T tile: 256 rows (c) x 64 halves (m)
#pragma unroll
        for (int it = 0; it < 16; it++) {
            int idx = tid + 256 * it;
            int c = idx >> 4, sg2 = idx & 15;
            *(uint2*)&VsT[c * V_PAD + sg2 * 4] =
                *(const uint2*)&g_VhT[((size_t)b * CDIM + c) * NPIX + m0 + sg2 * 4];
        }
        __syncthreads();

        // --- S = Q K^T (each warp: 16x32 region = 4 n-tiles x 2 k-steps) ---
#pragma unroll
        for (int j = 0; j < 4; j++) {
            float c0 = 0.f, c1 = 0.f, c2 = 0.f, c3 = 0.f;
#pragma unroll
            for (int s = 0; s < 2; s++) {
                const __half* kb = &Ks[(qk_cb + 8 * j + g) * QK_PAD + 2 * t + 16 * s];
                uint32_t b0 = *(const uint32_t*)kb;
                uint32_t b1 = *(const uint32_t*)(kb + 8);
                mma16816(c0, c1, c2, c3, qa[s][0], qa[s][1], qa[s][2], qa[s][3], b0, b1);
            }
            float* srow = &Ssm[(qk_rb + g) * S_PAD + qk_cb + 8 * j + 2 * t];
            srow[0] = c0; srow[1] = c1;
            srow += 8 * S_PAD;
            srow[0] = c2; srow[1] = c3;
        }
        __syncthreads();

        // --- online softmax: 4 partial threads per query row ---
        float lm = -INFINITY;
#pragma unroll
        for (int i = 0; i < 16; i++)
            lm = fmaxf(lm, Ssm[sq * S_PAD + part * 16 + i]);
        pmax[part * 64 + sq] = lm;
        __syncthreads();

        if (tid < 64) {
            float tm = fmaxf(fmaxf(pmax[tid], pmax[64 + tid]),
                             fmaxf(pmax[128 + tid], pmax[192 + tid]));
            float mnew = fmaxf(m_run, tm);
            alpha_reg = __expf(m_run - mnew);
            m_run = mnew;
            m_s[tid]   = mnew;
            alp_s[tid] = alpha_reg;
        }
        __syncthreads();

        {
            const float mn = m_s[sq];
            float ps = 0.f;
#pragma unroll
            for (int i = 0; i < 16; i += 2) {
                float p0 = __expf(Ssm[sq * S_PAD + part * 16 + i]     - mn);
                float p1 = __expf(Ssm[sq * S_PAD + part * 16 + i + 1] - mn);
                ps += p0 + p1;
                *(__half2*)&Ps[sq * P_PAD + part * 16 + i] = __floats2half2_rn(p0, p1);
            }
            psum[part * 64 + sq] = ps;
        }
        __syncthreads();

        if (tid < 64)
            l_run = l_run * alpha_reg
                  + psum[tid] + psum[64 + tid] + psum[128 + tid] + psum[192 + tid];

        // --- PV: rescale accumulators, then O += P V ---
        const float al0 = alp_s[pv_qb + g];
        const float al1 = alp_s[pv_qb + 8 + g];
        const float al2 = alp_s[pv_qb + 16 + g];
        const float al3 = alp_s[pv_qb + 24 + g];
#pragma unroll
        for (int j = 0; j < 8; j++) {
            acc[0][j][0] *= al0; acc[0][j][1] *= al0;
            acc[0][j][2] *= al1; acc[0][j][3] *= al1;
            acc[1][j][0] *= al2; acc[1][j][1] *= al2;
            acc[1][j][2] *= al3; acc[1][j][3] *= al3;
        }

#pragma unroll
        for (int s = 0; s < 4; s++) {
            uint32_t pa[2][4];
#pragma unroll
            for (int i = 0; i < 2; i++) {
                const __half* pb = &Ps[(pv_qb + 16 * i + g) * P_PAD + 2 * t + 16 * s];
                pa[i][0] = *(const uint32_t*)pb;
                pa[i][2] = *(const uint32_t*)(pb + 8);
                const __half* p8 = pb + 8 * P_PAD;
                pa[i][1] = *(const uint32_t*)p8;
                pa[i][3] = *(const uint32_t*)(p8 + 8);
            }
#pragma unroll
            for (int j = 0; j < 8; j++) {
                const __half* vb = &VsT[(pv_cb + 8 * j + g) * V_PAD + 2 * t + 16 * s];
                uint32_t b0 = *(const uint32_t*)vb;
                uint32_t b1 = *(const uint32_t*)(vb + 8);
                mma16816(acc[0][j][0], acc[0][j][1], acc[0][j][2], acc[0][j][3],
                         pa[0][0], pa[0][1], pa[0][2], pa[0][3], b0, b1);
                mma16816(acc[1][j][0], acc[1][j][1], acc[1][j][2], acc[1][j][3],
                         pa[1][0], pa[1][1], pa[1][2], pa[1][3], b0, b1);
            }
        }
    }

    // --- epilogue: scale by gamma / l, transpose through smem, store coalesced ---
    if (tid < 64) linv[tid] = 1.f / l_run;
    const float gamma0 = gamma[0];

#pragma unroll
    for (int h = 0; h < 2; h++) {
        __syncthreads();
        if ((pv_cb >> 7) == h) {
            const int cl = pv_cb & 127;
#pragma unroll
            for (int i = 0; i < 2; i++) {
                const int r0 = pv_qb + 16 * i + g;
                const int r1 = r0 + 8;
                const float s0 = linv[r0] * gamma0;
                const float s1 = linv[r1] * gamma0;
#pragma unroll
                for (int j = 0; j < 8; j++) {
                    const int c = cl + 8 * j + 2 * t;
                    Obuf[c * OB_PAD + r0]       = acc[i][j][0] * s0;
                    Obuf[(c + 1) * OB_PAD + r0] = acc[i][j][1] * s0;
                    Obuf[c * OB_PAD + r1]       = acc[i][j][2] * s1;
                    Obuf[(c + 1) * OB_PAD + r1] = acc[i][j][3] * s1;
                }
            }
        }
        __syncthreads();
#pragma unroll
        for (int it = 0; it < 32; it++) {
            int idx = tid + 256 * it;
            int c = idx >> 6, q = idx & 63;
            out[((size_t)b * CDIM + h * 128 + c) * NPIX + q0 + q] = Obuf[c * OB_PAD + q];
        }
    }
}

// ---------------------------------------------------------------------------
// Inputs: x, Wq, bq, Wk, bk, Wv, bv, gamma. Output: float32 [B,C,H,W].
// ---------------------------------------------------------------------------
extern "C" void kernel_launch(void* const* d_in, const int* in_sizes, int n_in,
                              void* d_out, int out_size)
{
    const float* x     = (const float*)d_in[0];
    const float* Wq    = (const float*)d_in[1];
    const float* bq    = (const float*)d_in[2];
    const float* Wk    = (const float*)d_in[3];
    const float* bk    = (const float*)d_in[4];
    const float* Wv    = (const float*)d_in[5];
    const float* bv    = (const float*)d_in[6];
    const float* gamma = (const float*)d_in[7];
    float* out = (float*)d_out;

    // Opt in to >48KB dynamic smem (idempotent; persists across calls)
    cudaFuncSetAttribute(attn_kernel,
                         cudaFuncAttributeMaxDynamicSharedMemorySize, SMEM_TOTAL);

    proj_kernel<<<dim3(NPIX / 32, BATCH), 256>>>(x, Wq, bq, Wk, bk, Wv, bv);
    attn_kernel<<<dim3(NPIX / QTILE, BATCH), 256, SMEM_TOTAL>>>(out, gamma);
}

// round 3
// speedup vs baseline: 4.2096x; 1.0001x over previous
#include <cuda_runtime.h>
#include <cuda_fp16.h>
#include <cuda_bf16.h>
#include <math.h>
#include <stdint.h>

#define BATCH 4
#define CDIM  256
#define CQK   32
#define NPIX  4096   // 64*64

// fp16 scratch (static device globals: allowed)
__device__ __half g_Qh[BATCH * NPIX * CQK];
__device__ __half g_Kh[BATCH * NPIX * CQK];
__device__ __half g_VhT[(size_t)BATCH * CDIM * NPIX];   // [B][C][N] transposed

// ---------------------------------------------------------------------------
// Projection kernel (fp32 compute, fp16 outputs).
// ---------------------------------------------------------------------------
__global__ __launch_bounds__(256) void proj_kernel(
    const float* __restrict__ x,
    const float* __restrict__ Wq, const float* __restrict__ bq,
    const float* __restrict__ Wk, const float* __restrict__ bk,
    const float* __restrict__ Wv, const float* __restrict__ bv)
{
    const int b  = blockIdx.y;
    const int n0 = blockIdx.x * 32;

    __shared__ float xs[32 * 260];

    const int tid = threadIdx.x;
    for (int idx = tid; idx < 32 * 256; idx += 256) {
        int i = idx & 31;
        int c = idx >> 5;
        xs[i * 260 + c] = x[(b * CDIM + c) * NPIX + n0 + i];
    }
    __syncthreads();

    const int n = tid & 31;
    const int g = tid >> 5;

    float accq[4] = {0.f, 0.f, 0.f, 0.f};
    float acck[4] = {0.f, 0.f, 0.f, 0.f};
    float accv[32];
#pragma unroll
    for (int j = 0; j < 32; j++) accv[j] = 0.f;

    const float* xrow = &xs[n * 260];

#pragma unroll 2
    for (int c = 0; c < 256; c += 4) {
        const float4 xv = *(const float4*)&xrow[c];
#pragma unroll
        for (int j = 0; j < 4; j++) {
            const float4 w = *(const float4*)&Wq[(g * 4 + j) * CDIM + c];
            accq[j] += xv.x * w.x + xv.y * w.y + xv.z * w.z + xv.w * w.w;
        }
#pragma unroll
        for (int j = 0; j < 4; j++) {
            const float4 w = *(const float4*)&Wk[(g * 4 + j) * CDIM + c];
            acck[j] += xv.x * w.x + xv.y * w.y + xv.z * w.z + xv.w * w.w;
        }
#pragma unroll
        for (int j = 0; j < 32; j++) {
            const float4 w = *(const float4*)&Wv[(g * 32 + j) * CDIM + c];
            accv[j] += xv.x * w.x + xv.y * w.y + xv.z * w.z + xv.w * w.w;
        }
    }

    const int nglob = b * NPIX + n0 + n;
#pragma unroll
    for (int j = 0; j < 4; j++) {
        g_Qh[nglob * CQK + g * 4 + j] = __float2half_rn(accq[j] + bq[g * 4 + j]);
        g_Kh[nglob * CQK + g * 4 + j] = __float2half_rn(acck[j] + bk[g * 4 + j]);
    }
#pragma unroll
    for (int j = 0; j < 32; j++) {
        g_VhT[((size_t)b * CDIM + g * 32 + j) * NPIX + n0 + n] =
            __float2half_rn(accv[j] + bv[g * 32 + j]);
    }
}

// ---------------------------------------------------------------------------
// Flash attention with mma.sync.m16n8k16 fp16 (fp32 accumulate).
// CTA: 64 queries, 256 threads (8 warps). Key tiles of 64.
// ---------------------------------------------------------------------------
#define QTILE  64
#define KTILE  64
#define QK_PAD 40   // halves per row, Qs/Ks (conflict-free fragment loads)
#define V_PAD  72   // halves per row, VsT
#define S_PAD  66   // floats per row, Ssm
#define P_PAD  70   // halves per row, Ps

// smem byte offsets
#define OFF_QS    0        // 64*40*2   = 5120
#define OFF_KS    5120     // 5120
#define OFF_VST   10240    // 256*72*2  = 36864 (also aliased as Obuf: 128*66*4)
#define OFF_SSM   47104    // 64*66*4   = 16896
#define OFF_PS    64000    // 64*70*2   = 8960
#define OFF_PMAX  72960    // 4*64*4
#define OFF_PSUM  73984    // 4*64*4
#define OFF_MS    75008    // 64*4
#define OFF_ALPHA 75264    // 64*4
#define OFF_LINV  75520    // 64*4
#define SMEM_TOTAL 75776
#define OB_PAD 66

__device__ __forceinline__ void mma16816(
    float& c0, float& c1, float& c2, float& c3,
    uint32_t a0, uint32_t a1, uint32_t a2, uint32_t a3,
    uint32_t b0, uint32_t b1)
{
    asm volatile(
        "mma.sync.aligned.m16n8k16.row.col.f32.f16.f16.f32 "
        "{%0,%1,%2,%3}, {%4,%5,%6,%7}, {%8,%9}, {%0,%1,%2,%3};\n"
        : "+f"(c0), "+f"(c1), "+f"(c2), "+f"(c3)
        : "r"(a0), "r"(a1), "r"(a2), "r"(a3), "r"(b0), "r"(b1));
}

__global__ __launch_bounds__(256, 2) void attn_kernel(
    float* __restrict__ out, const float* __restrict__ gamma)
{
    extern __shared__ char sm[];
    __half* Qs    = (__half*)(sm + OFF_QS);
    __half* Ks    = (__half*)(sm + OFF_KS);
    __half* VsT   = (__half*)(sm + OFF_VST);
    float*  Ssm   = (float*)(sm + OFF_SSM);
    __half* Ps    = (__half*)(sm + OFF_PS);
    float*  pmax  = (float*)(sm + OFF_PMAX);
    float*  psum  = (float*)(sm + OFF_PSUM);
    float*  m_s   = (float*)(sm + OFF_MS);
    float*  alp_s = (float*)(sm + OFF_ALPHA);
    float*  linv  = (float*)(sm + OFF_LINV);
    float*  Obuf  = (float*)(sm + OFF_VST);   // alias, used only in epilogue

    const int b   = blockIdx.y;
    const int q0  = blockIdx.x * QTILE;
    const int tid = threadIdx.x;
    const int w   = tid >> 5;
    const int lane = tid & 31;
    const int g = lane >> 2;   // mma groupID
    const int t = lane & 3;    // thread-in-group

    const size_t bN = (size_t)b * NPIX;

    // QK-phase warp mapping: S rows 16*(w&3), cols 32*(w>>2)
    const int qk_rb = 16 * (w & 3);
    const int qk_cb = 32 * (w >> 2);
    // PV-phase warp mapping: out rows 32*(w&1), cols 64*(w>>1)
    const int pv_qb = 32 * (w & 1);
    const int pv_cb = 64 * (w >> 1);

    // softmax mapping
    const int sq   = tid & 63;
    const int part = tid >> 6;

    // Load Q tile once: 64 rows x 32 halves
    {
        int row = tid >> 2, seg = tid & 3;
        *(uint4*)&Qs[row * QK_PAD + seg * 8] =
            *(const uint4*)&g_Qh[(bN + q0 + row) * CQK + seg * 8];
    }
    __syncthreads();

    // Preload Q fragments (persistent across all key tiles)
    uint32_t qa[2][4];
#pragma unroll
    for (int s = 0; s < 2; s++) {
        const __half* base = &Qs[(qk_rb + g) * QK_PAD + 2 * t + 16 * s];
        qa[s][0] = *(const uint32_t*)base;
        qa[s][2] = *(const uint32_t*)(base + 8);
        const __half* b8 = base + 8 * QK_PAD;
        qa[s][1] = *(const uint32_t*)b8;
        qa[s][3] = *(const uint32_t*)(b8 + 8);
    }

    float acc[2][8][4];
#pragma unroll
    for (int i = 0; i < 2; i++)
#pragma unroll
        for (int j = 0; j < 8; j++)
#pragma unroll
            for (int k = 0; k < 4; k++) acc[i][j][k] = 0.f;

    float m_run = -INFINITY, l_run = 0.f, alpha_reg = 0.f;

    for (int kt = 0; kt < NPIX / KTILE; kt++) {
        const int m0 = kt * KTILE;
        __syncthreads();   // previous iter's PV reads done before overwriting tiles

        // Load K tile: 64 x 32 halves
        {
            int row = tid >> 2, seg = tid & 3;
            *(uint4*)&Ks[row * QK_PAD + seg * 8] =
                *(const uint4*)&g_Kh[(bN + m0 + row) * CQK + seg * 8];
        }
        // Load V^T tile: 256 rows (c) x 64 halves (m)
#pragma unroll
        for (int it = 0; it < 16; it++) {
            int idx = tid + 256 * it;
            int c = idx >> 4, sg2 = idx & 15;
            *(uint2*)&VsT[c * V_PAD + sg2 * 4] =
                *(const uint2*)&g_VhT[((size_t)b * CDIM + c) * NPIX + m0 + sg2 * 4];
        }
        __syncthreads();

        // --- S = Q K^T (each warp: 16x32 region = 4 n-tiles x 2 k-steps) ---
#pragma unroll
        for (int j = 0; j < 4; j++) {
            float c0 = 0.f, c1 = 0.f, c2 = 0.f, c3 = 0.f;
#pragma unroll
            for (int s = 0; s < 2; s++) {
                const __half* kb = &Ks[(qk_cb + 8 * j + g) * QK_PAD + 2 * t + 16 * s];
                uint32_t b0 = *(const uint32_t*)kb;
                uint32_t b1 = *(const uint32_t*)(kb + 8);
                mma16816(c0, c1, c2, c3, qa[s][0], qa[s][1], qa[s][2], qa[s][3], b0, b1);
            }
            float* srow = &Ssm[(qk_rb + g) * S_PAD + qk_cb + 8 * j + 2 * t];
            srow[0] = c0; srow[1] = c1;
            srow += 8 * S_PAD;
            srow[0] = c2; srow[1] = c3;
        }
        __syncthreads();

        // --- online softmax: 4 partial threads per query row ---
        float lm = -INFINITY;
#pragma unroll
        for (int i = 0; i < 16; i++)
            lm = fmaxf(lm, Ssm[sq * S_PAD + part * 16 + i]);
        pmax[part * 64 + sq] = lm;
        __syncthreads();

        if (tid < 64) {
            float tm = fmaxf(fmaxf(pmax[tid], pmax[64 + tid]),
                             fmaxf(pmax[128 + tid], pmax[192 + tid]));
            float mnew = fmaxf(m_run, tm);
            alpha_reg = __expf(m_run - mnew);
            m_run = mnew;
            m_s[tid]   = mnew;
            alp_s[tid] = alpha_reg;
        }
        __syncthreads();

        {
            const float mn = m_s[sq];
            float ps = 0.f;
#pragma unroll
            for (int i = 0; i < 16; i += 2) {
                float p0 = __expf(Ssm[sq * S_PAD + part * 16 + i]     - mn);
                float p1 = __expf(Ssm[sq * S_PAD + part * 16 + i + 1] - mn);
                ps += p0 + p1;
                *(__half2*)&Ps[sq * P_PAD + part * 16 + i] = __floats2half2_rn(p0, p1);
            }
            psum[part * 64 + sq] = ps;
        }
        __syncthreads();

        if (tid < 64)
            l_run = l_run * alpha_reg
                  + psum[tid] + psum[64 + tid] + psum[128 + tid] + psum[192 + tid];

        // --- PV: rescale accumulators, then O += P V ---
        const float al0 = alp_s[pv_qb + g];
        const float al1 = alp_s[pv_qb + 8 + g];
        const float al2 = alp_s[pv_qb + 16 + g];
        const float al3 = alp_s[pv_qb + 24 + g];
#pragma unroll
        for (int j = 0; j < 8; j++) {
            acc[0][j][0] *= al0; acc[0][j][1] *= al0;
            acc[0][j][2] *= al1; acc[0][j][3] *= al1;
            acc[1][j][0] *= al2; acc[1][j][1] *= al2;
            acc[1][j][2] *= al3; acc[1][j][3] *= al3;
        }

#pragma unroll
        for (int s = 0; s < 4; s++) {
            uint32_t pa[2][4];
#pragma unroll
            for (int i = 0; i < 2; i++) {
                const __half* pb = &Ps[(pv_qb + 16 * i + g) * P_PAD + 2 * t + 16 * s];
                pa[i][0] = *(const uint32_t*)pb;
                pa[i][2] = *(const uint32_t*)(pb + 8);
                const __half* p8 = pb + 8 * P_PAD;
                pa[i][1] = *(const uint32_t*)p8;
                pa[i][3] = *(const uint32_t*)(p8 + 8);
            }
#pragma unroll
            for (int j = 0; j < 8; j++) {
                const __half* vb = &VsT[(pv_cb + 8 * j + g) * V_PAD + 2 * t + 16 * s];
                uint32_t b0 = *(const uint32_t*)vb;
                uint32_t b1 = *(const uint32_t*)(vb + 8);
                mma16816(acc[0][j][0], acc[0][j][1], acc[0][j][2], acc[0][j][3],
                         pa[0][0], pa[0][1], pa[0][2], pa[0][3], b0, b1);
                mma16816(acc[1][j][0], acc[1][j][1], acc[1][j][2], acc[1][j][3],
                         pa[1][0], pa[1][1], pa[1][2], pa[1][3], b0, b1);
            }
        }
    }

    // --- epilogue: scale by gamma / l, transpose through smem, store coalesced ---
    if (tid < 64) linv[tid] = 1.f / l_run;
    const float gamma0 = gamma[0];

#pragma unroll
    for (int h = 0; h < 2; h++) {
        __syncthreads();
        if ((pv_cb >> 7) == h) {
            const int cl = pv_cb & 127;
#pragma unroll
            for (int i = 0; i < 2; i++) {
                const int r0 = pv_qb + 16 * i + g;
                const int r1 = r0 + 8;
                const float s0 = linv[r0] * gamma0;
                const float s1 = linv[r1] * gamma0;
#pragma unroll
                for (int j = 0; j < 8; j++) {
                    const int c = cl + 8 * j + 2 * t;
                    Obuf[c * OB_PAD + r0]       = acc[i][j][0] * s0;
                    Obuf[(c + 1) * OB_PAD + r0] = acc[i][j][1] * s0;
                    Obuf[c * OB_PAD + r1]       = acc[i][j][2] * s1;
                    Obuf[(c + 1) * OB_PAD + r1] = acc[i][j][3] * s1;
                }
            }
        }
        __syncthreads();
#pragma unroll
        for (int it = 0; it < 32; it++) {
            int idx = tid + 256 * it;
            int c = idx >> 6, q = idx & 63;
            out[((size_t)b * CDIM + h * 128 + c) * NPIX + q0 + q] = Obuf[c * OB_PAD + q];
        }
    }
}

// ---------------------------------------------------------------------------
// Inputs: x, Wq, bq, Wk, bk, Wv, bv, gamma. Output: float32 [B,C,H,W].
// ---------------------------------------------------------------------------
extern "C" void kernel_launch(void* const* d_in, const int* in_sizes, int n_in,
                              void* d_out, int out_size)
{
    const float* x     = (const float*)d_in[0];
    const float* Wq    = (const float*)d_in[1];
    const float* bq    = (const float*)d_in[2];
    const float* Wk    = (const float*)d_in[3];
    const float* bk    = (const float*)d_in[4];
    const float* Wv    = (const float*)d_in[5];
    const float* bv    = (const float*)d_in[6];
    const float* gamma = (const float*)d_in[7];
    float* out = (float*)d_out;

    // Opt in to >48KB dynamic smem (idempotent; persists across calls)
    cudaFuncSetAttribute(attn_kernel,
                         cudaFuncAttributeMaxDynamicSharedMemorySize, SMEM_TOTAL);

    proj_kernel<<<dim3(NPIX / 32, BATCH), 256>>>(x, Wq, bq, Wk, bk, Wv, bv);
    attn_kernel<<<dim3(NPIX / QTILE, BATCH), 256, SMEM_TOTAL>>>(out, gamma);
}